// round 7
// baseline (speedup 1.0000x reference)
#include <cuda_runtime.h>
#include <cstdint>

#define B_SZ 64
#define T_SZ 2048
#define I_SZ 256
#define H_SZ 256
#define O_SZ 128
#define M_SZ (B_SZ * T_SZ)   // 131072 rows

// Scratch (device globals: no allocations allowed)
__device__ float g_xp1[(size_t)M_SZ * H_SZ];   // 128 MB
__device__ float g_h1 [(size_t)M_SZ * H_SZ];   // 128 MB
__device__ unsigned g_flag[64];                // per (scan1 pair, rank) progress

// ---------------------------------------------------------------------------
union f2u { float2 f; unsigned long long u; };

__device__ __forceinline__ float2 ffma2(float2 a, float2 b, float2 c) {
    f2u A, Bv, C;
    A.f = a; Bv.f = b; C.f = c;
    asm("fma.rn.f32x2 %0, %1, %2, %3;"
        : "=l"(C.u) : "l"(A.u), "l"(Bv.u), "l"(C.u));
    return C.f;
}

// Branch-free fast tanh (validated: rel_err 4.4e-7 vs 1e-3 budget)
__device__ __forceinline__ float fast_tanh(float x) {
    float ax = fabsf(x);
    float e  = __expf(-2.0f * ax);
    float t  = __fdividef(1.0f - e, 1.0f + e);
    return copysignf(t, x);
}

__device__ __forceinline__ uint32_t smem_u32(const void* p) {
    return (uint32_t)__cvta_generic_to_shared(p);
}
__device__ __forceinline__ uint32_t mapa_peer(uint32_t a, unsigned peer) {
    uint32_t r;
    asm("mapa.shared::cluster.u32 %0, %1, %2;" : "=r"(r) : "r"(a), "r"(peer));
    return r;
}
__device__ __forceinline__ void mbar_wait_acq_cluster(uint32_t mbar, uint32_t parity) {
    asm volatile(
        "{\n\t.reg .pred P;\n\t"
        "W_%=:\n\t"
        "mbarrier.try_wait.parity.acquire.cluster.shared::cta.b64 P, [%0], %1;\n\t"
        "@!P bra W_%=;\n\t}"
        :: "r"(mbar), "r"(parity) : "memory");
}
__device__ __forceinline__ void flag_release(unsigned* p, unsigned v) {
    asm volatile("st.release.gpu.global.u32 [%0], %1;" :: "l"(p), "r"(v) : "memory");
}
__device__ __forceinline__ unsigned flag_acquire(const unsigned* p) {
    unsigned v;
    asm volatile("ld.acquire.gpu.global.u32 %0, [%1];" : "=r"(v) : "l"(p) : "memory");
    return v;
}

// ---------------------------------------------------------------------------
// SGEMM with fused double-bias (unchanged). Tile (0,0) also resets g_flag.
// ---------------------------------------------------------------------------
__global__ __launch_bounds__(256, 2)
void sgemm_bias_kernel(const float* __restrict__ A,
                       const float* __restrict__ W,
                       const float* __restrict__ bias_a,
                       const float* __restrict__ bias_b,
                       float* __restrict__ C, int K, int N,
                       unsigned* __restrict__ flags)
{
    constexpr int BM = 128, BN = 128, BK = 16;
    __shared__ float As[BK][BM];
    __shared__ float Bs[BK][BN];

    int tid = threadIdx.x;
    if (flags && blockIdx.x == 0 && blockIdx.y == 0 && tid < 64)
        flags[tid] = 0u;

    int bm = blockIdx.y * BM;
    int bn = blockIdx.x * BN;
    int tm = tid >> 4;
    int tn = tid & 15;

    float2 acc[8][4];
    #pragma unroll
    for (int i = 0; i < 8; i++)
        #pragma unroll
        for (int j = 0; j < 4; j++) acc[i][j] = make_float2(0.f, 0.f);

    const float* Ab = A + (size_t)bm * K;
    const float* Wb = W + (size_t)bn * K;

    for (int kt = 0; kt < K; kt += BK) {
        #pragma unroll
        for (int it = 0; it < 2; it++) {
            int lid = tid * 2 + it;
            int row = lid >> 2, c4 = lid & 3;
            float4 v = *(const float4*)(Ab + (size_t)row * K + kt + c4 * 4);
            As[c4 * 4 + 0][row] = v.x;
            As[c4 * 4 + 1][row] = v.y;
            As[c4 * 4 + 2][row] = v.z;
            As[c4 * 4 + 3][row] = v.w;
        }
        #pragma unroll
        for (int it = 0; it < 2; it++) {
            int lid = tid * 2 + it;
            int row = lid >> 2, c4 = lid & 3;
            float4 v = *(const float4*)(Wb + (size_t)row * K + kt + c4 * 4);
            Bs[c4 * 4 + 0][row] = v.x;
            Bs[c4 * 4 + 1][row] = v.y;
            Bs[c4 * 4 + 2][row] = v.z;
            Bs[c4 * 4 + 3][row] = v.w;
        }
        __syncthreads();

        #pragma unroll
        for (int kk = 0; kk < BK; kk++) {
            float4 a0 = *(const float4*)&As[kk][tm * 8];
            float4 a1 = *(const float4*)&As[kk][tm * 8 + 4];
            float4 b0 = *(const float4*)&Bs[kk][tn * 8];
            float4 b1 = *(const float4*)&Bs[kk][tn * 8 + 4];
            float av[8] = {a0.x, a0.y, a0.z, a0.w, a1.x, a1.y, a1.z, a1.w};
            float2 bv[4] = {make_float2(b0.x, b0.y), make_float2(b0.z, b0.w),
                            make_float2(b1.x, b1.y), make_float2(b1.z, b1.w)};
            #pragma unroll
            for (int i = 0; i < 8; i++) {
                float2 ai = make_float2(av[i], av[i]);
                #pragma unroll
                for (int j = 0; j < 4; j++)
                    acc[i][j] = ffma2(ai, bv[j], acc[i][j]);
            }
        }
        __syncthreads();
    }

    float2 bb[4];
    #pragma unroll
    for (int j = 0; j < 4; j++) {
        int n = bn + tn * 8 + j * 2;
        bb[j] = make_float2(bias_a[n] + bias_b[n], bias_a[n + 1] + bias_b[n + 1]);
    }
    #pragma unroll
    for (int i = 0; i < 8; i++) {
        int m = bm + tm * 8 + i;
        float* Crow = C + (size_t)m * N + bn + tn * 8;
        #pragma unroll
        for (int j = 0; j < 4; j++) {
            float2 v = make_float2(acc[i][j].x + bb[j].x, acc[i][j].y + bb[j].y);
            *(float2*)(Crow + j * 2) = v;
        }
    }
}

// ---------------------------------------------------------------------------
// Fused scan kernel. Grid = 128 CTAs (cluster 2), 1 CTA/SM -> all co-resident.
//   cluster pairs 0..31  : LAYER-1 scan, 2 batches per pair (b=2q, 2q+1).
//   cluster pairs 32..63 : LAYER-2 scan, 2 batches per pair, computes its own
//                          W_ih2 GEMV (xp2 never materialized), consumes h1
//                          via global memory + release/acquire flags.
// ---------------------------------------------------------------------------
__global__ void __cluster_dims__(2, 1, 1) __launch_bounds__(512, 1)
fused_scan_kernel(const float* __restrict__ W_hh1,
                  const float* __restrict__ xp1,
                  float* __restrict__ h1,
                  const float* __restrict__ W_ih2,
                  const float* __restrict__ W_hh2,
                  const float* __restrict__ b_ih2,
                  const float* __restrict__ b_hh2,
                  float* __restrict__ out,
                  unsigned* __restrict__ flags)
{
    // role-specific SMEM (both declared; ~10 KB total, occupancy target is 1)
    __shared__ alignas(16) float hbuf[2][2][4 * 68];      // scan1: [batch][phase]
    __shared__ alignas(16) float h1s[2][8 * 36];          // scan2: staged h1_t
    __shared__ alignas(16) float obuf[2][2][8 * 20];      // scan2: [batch][phase]
    __shared__ alignas(8) unsigned long long mbar;

    int cid = blockIdx.x;
    int tid = threadIdx.x;
    unsigned r;
    asm("mov.u32 %0, %%cluster_ctarank;" : "=r"(r));
    unsigned peer = r ^ 1u;
    int pairIdx = cid >> 1;

    uint32_t mb = smem_u32(&mbar);
    if (tid == 0)
        asm volatile("mbarrier.init.shared.b64 [%0], %1;" :: "r"(mb), "r"(1) : "memory");
    uint32_t rmb = mapa_peer(mb, peer);

    if (pairIdx < 32) {
        // =================== LAYER-1 ROLE (2 batches) =====================
        int q  = pairIdx;
        int b0 = 2 * q, b1 = 2 * q + 1;
        int o_local = tid >> 2;
        int c = tid & 3;
        int o_global = (int)r * 128 + o_local;

        float2 w2[32];
        {
            const float4* wp = (const float4*)(W_hh1 + (size_t)o_global * H_SZ + c * 64);
            #pragma unroll
            for (int j = 0; j < 16; j++) {
                int jj = (j + c * 4) & 15;
                float4 v = wp[jj];
                w2[2 * j]     = make_float2(v.x, v.y);
                w2[2 * j + 1] = make_float2(v.z, v.w);
            }
        }

        for (int i = tid; i < 2 * 2 * 4 * 68; i += 512) ((float*)hbuf)[i] = 0.f;

        int wpos = (o_global >> 6) * 68 + (o_global & 63);
        uint32_t rem[2][2];
        #pragma unroll
        for (int bb = 0; bb < 2; bb++)
            #pragma unroll
            for (int ph = 0; ph < 2; ph++)
                rem[bb][ph] = mapa_peer(smem_u32(&hbuf[bb][ph][wpos]), peer);

        const float* xpb0 = xp1 + (size_t)b0 * T_SZ * H_SZ + o_global;
        const float* xpb1 = xp1 + (size_t)b1 * T_SZ * H_SZ + o_global;
        float* hob0 = h1 + (size_t)b0 * T_SZ * H_SZ + o_global;
        float* hob1 = h1 + (size_t)b1 * T_SZ * H_SZ + o_global;
        unsigned* myflag = &flags[2 * q + r];

        float pf0[4], pf1[4];
        #pragma unroll
        for (int i = 0; i < 4; i++) {
            pf0[i] = __ldg(xpb0 + (size_t)i * H_SZ);
            pf1[i] = __ldg(xpb1 + (size_t)i * H_SZ);
        }

        asm volatile("barrier.cluster.arrive.aligned;\n\tbarrier.cluster.wait.aligned;" ::: "memory");

        int p = 0;
        #pragma unroll 2
        for (int t = 0; t < T_SZ; t++) {
            if (t > 0)
                mbar_wait_acq_cluster(mb, (uint32_t)((t - 1) & 1));

            float xv0 = pf0[t & 3], xv1 = pf1[t & 3];
            int tn4 = (t + 4 < T_SZ) ? (t + 4) : (T_SZ - 1);
            pf0[t & 3] = __ldg(xpb0 + (size_t)tn4 * H_SZ);
            pf1[t & 3] = __ldg(xpb1 + (size_t)tn4 * H_SZ);

            const float* hbA = &hbuf[0][p][c * 68];
            const float* hbB = &hbuf[1][p][c * 68];
            float2 a0 = make_float2(0.f, 0.f), a1 = a0, a2 = a0, a3 = a0;
            float2 d0 = a0, d1 = a0, d2 = a0, d3 = a0;
            #pragma unroll
            for (int j = 0; j < 16; j++) {
                int jj = (j + c * 4) & 15;
                float4 hv = *(const float4*)(hbA + jj * 4);
                float4 gv = *(const float4*)(hbB + jj * 4);
                float2 wA = w2[2 * j], wB = w2[2 * j + 1];
                if (j & 1) {
                    a2 = ffma2(make_float2(hv.x, hv.y), wA, a2);
                    a3 = ffma2(make_float2(hv.z, hv.w), wB, a3);
                    d2 = ffma2(make_float2(gv.x, gv.y), wA, d2);
                    d3 = ffma2(make_float2(gv.z, gv.w), wB, d3);
                } else {
                    a0 = ffma2(make_float2(hv.x, hv.y), wA, a0);
                    a1 = ffma2(make_float2(hv.z, hv.w), wB, a1);
                    d0 = ffma2(make_float2(gv.x, gv.y), wA, d0);
                    d1 = ffma2(make_float2(gv.z, gv.w), wB, d1);
                }
            }
            float s0 = (a0.x + a1.x + a2.x + a3.x) + (a0.y + a1.y + a2.y + a3.y);
            float s1 = (d0.x + d1.x + d2.x + d3.x) + (d0.y + d1.y + d2.y + d3.y);
            s0 += __shfl_xor_sync(0xffffffffu, s0, 1);
            s1 += __shfl_xor_sync(0xffffffffu, s1, 1);
            s0 += __shfl_xor_sync(0xffffffffu, s0, 2);
            s1 += __shfl_xor_sync(0xffffffffu, s1, 2);

            float v0 = fast_tanh(s0 + xv0);
            float v1 = fast_tanh(s1 + xv1);
            hbuf[0][p ^ 1][wpos] = v0;
            hbuf[1][p ^ 1][wpos] = v1;
            if (c == 0) {
                asm volatile("st.shared::cluster.f32 [%0], %1;" :: "r"(rem[0][p ^ 1]), "f"(v0) : "memory");
                asm volatile("st.shared::cluster.f32 [%0], %1;" :: "r"(rem[1][p ^ 1]), "f"(v1) : "memory");
                hob0[(size_t)t * H_SZ] = v0;
                hob1[(size_t)t * H_SZ] = v1;
            }
            __syncthreads();
            if (tid == 0) {
                flag_release(myflag, (unsigned)(t + 1));
                asm volatile("mbarrier.arrive.release.cluster.shared::cluster.b64 _, [%0];"
                             :: "r"(rmb) : "memory");
            }
            p ^= 1;
        }
        asm volatile("barrier.cluster.arrive.aligned;\n\tbarrier.cluster.wait.aligned;" ::: "memory");
    } else {
        // =================== LAYER-2 ROLE (2 batches) =====================
        int q  = pairIdx - 32;              // producer pair index
        int b0 = 2 * q, b1 = 2 * q + 1;
        int og = tid >> 3;                  // 0..63 output group
        int j  = tid & 7;                   // 8 lanes per output
        int o_global = (int)r * 64 + og;

        // Register-resident layer-2 weights: 32 ih + 16 hh floats per thread
        float2 wih[16], whh[8];
        {
            const float4* wp = (const float4*)(W_ih2 + (size_t)o_global * H_SZ + 32 * j);
            #pragma unroll
            for (int i = 0; i < 8; i++) {
                float4 v = wp[i];
                wih[2 * i]     = make_float2(v.x, v.y);
                wih[2 * i + 1] = make_float2(v.z, v.w);
            }
            const float4* hp = (const float4*)(W_hh2 + (size_t)o_global * O_SZ + 16 * j);
            #pragma unroll
            for (int i = 0; i < 4; i++) {
                float4 v = hp[i];
                whh[2 * i]     = make_float2(v.x, v.y);
                whh[2 * i + 1] = make_float2(v.z, v.w);
            }
        }
        float bias_o = b_ih2[o_global] + b_hh2[o_global];

        for (int i = tid; i < 2 * 2 * 8 * 20; i += 512) ((float*)obuf)[i] = 0.f;

        int wq = (o_global >> 4) * 20 + (o_global & 15);
        uint32_t remo[2][2];
        #pragma unroll
        for (int bb = 0; bb < 2; bb++)
            #pragma unroll
            for (int ph = 0; ph < 2; ph++)
                remo[bb][ph] = mapa_peer(smem_u32(&obuf[bb][ph][wq]), peer);

        const float* h1b0 = h1 + (size_t)b0 * T_SZ * H_SZ;
        const float* h1b1 = h1 + (size_t)b1 * T_SZ * H_SZ;
        float* ob0 = out + (size_t)b0 * T_SZ * O_SZ + o_global;
        float* ob1 = out + (size_t)b1 * T_SZ * O_SZ + o_global;
        const unsigned* f0 = &flags[2 * q];
        const unsigned* f1 = &flags[2 * q + 1];

        asm volatile("barrier.cluster.arrive.aligned;\n\tbarrier.cluster.wait.aligned;" ::: "memory");

        int p = 0;
        for (int t = 0; t < T_SZ; t++) {
            if (t > 0)
                mbar_wait_acq_cluster(mb, (uint32_t)((t - 1) & 1));

            // wait for full h1_t (both producer CTAs of pair q)
            if (tid < 2) {
                const unsigned* fp = tid ? f1 : f0;
                while (flag_acquire(fp) < (unsigned)(t + 1)) { __nanosleep(40); }
            }
            __syncthreads();

            // stage h1_t for both batches into padded SMEM chunks
            if (tid < 128) {
                int bb = tid >> 6;          // 0 or 1
                int k  = tid & 63;          // float4 index 0..63
                const float* src = (bb ? h1b1 : h1b0) + (size_t)t * H_SZ + 4 * k;
                float4 v = *(const float4*)src;
                *(float4*)&h1s[bb][36 * (k >> 3) + 4 * (k & 7)] = v;
            }
            __syncthreads();

            #pragma unroll
            for (int bb = 0; bb < 2; bb++) {
                const float4* hp = (const float4*)&h1s[bb][36 * j];
                const float4* op = (const float4*)&obuf[bb][p][20 * j];
                float2 a0 = make_float2(0.f, 0.f), a1 = a0;
                #pragma unroll
                for (int i = 0; i < 8; i++) {
                    float4 hv = hp[i];
                    a0 = ffma2(make_float2(hv.x, hv.y), wih[2 * i],     a0);
                    a1 = ffma2(make_float2(hv.z, hv.w), wih[2 * i + 1], a1);
                }
                #pragma unroll
                for (int i = 0; i < 4; i++) {
                    float4 ov = op[i];
                    a0 = ffma2(make_float2(ov.x, ov.y), whh[2 * i],     a0);
                    a1 = ffma2(make_float2(ov.z, ov.w), whh[2 * i + 1], a1);
                }
                float s = (a0.x + a1.x) + (a0.y + a1.y);
                s += __shfl_xor_sync(0xffffffffu, s, 1);
                s += __shfl_xor_sync(0xffffffffu, s, 2);
                s += __shfl_xor_sync(0xffffffffu, s, 4);
                float v = fast_tanh(s + bias_o);
                if (j == 0) {
                    obuf[bb][p ^ 1][wq] = v;
                    asm volatile("st.shared::cluster.f32 [%0], %1;"
                                 :: "r"(remo[bb][p ^ 1]), "f"(v) : "memory");
                }
                if (j == 1)
                    (bb ? ob1 : ob0)[(size_t)t * O_SZ] = v;
            }
            __syncthreads();
            if (tid == 0)
                asm volatile("mbarrier.arrive.release.cluster.shared::cluster.b64 _, [%0];"
                             :: "r"(rmb) : "memory");
            p ^= 1;
        }
        asm volatile("barrier.cluster.arrive.aligned;\n\tbarrier.cluster.wait.aligned;" ::: "memory");
    }
}

// ---------------------------------------------------------------------------
extern "C" void kernel_launch(void* const* d_in, const int* in_sizes, int n_in,
                              void* d_out, int out_size)
{
    const float* x     = (const float*)d_in[0];
    const float* W_ih1 = (const float*)d_in[1];
    const float* W_hh1 = (const float*)d_in[2];
    const float* b_ih1 = (const float*)d_in[3];
    const float* b_hh1 = (const float*)d_in[4];
    const float* W_ih2 = (const float*)d_in[5];
    const float* W_hh2 = (const float*)d_in[6];
    const float* b_ih2 = (const float*)d_in[7];
    const float* b_hh2 = (const float*)d_in[8];
    float* out = (float*)d_out;

    float *xp1, *h1;
    unsigned* flags;
    cudaGetSymbolAddress((void**)&xp1,   g_xp1);
    cudaGetSymbolAddress((void**)&h1,    g_h1);
    cudaGetSymbolAddress((void**)&flags, g_flag);

    // Phase 1: xp1 = x @ W_ih1^T + (b_ih1 + b_hh1); also resets flags.
    dim3 g1(H_SZ / 128, M_SZ / 128);
    sgemm_bias_kernel<<<g1, 256>>>(x, W_ih1, b_ih1, b_hh1, xp1, I_SZ, H_SZ, flags);

    // Phase 2: fused layer-1 + layer-2 scans (producer/consumer overlap).
    fused_scan_kernel<<<128, 512>>>(W_hh1, xp1, h1,
                                    W_ih2, W_hh2, b_ih2, b_hh2, out, flags);
}

// round 8
// speedup vs baseline: 1.5092x; 1.5092x over previous
#include <cuda_runtime.h>
#include <cstdint>

#define B_SZ 64
#define T_SZ 2048
#define I_SZ 256
#define H_SZ 256
#define O_SZ 128
#define M_SZ (B_SZ * T_SZ)   // 131072 rows

// Scratch (device globals: no allocations allowed)
__device__ float g_xp1[(size_t)M_SZ * H_SZ];   // 128 MB
__device__ float g_h1 [(size_t)M_SZ * H_SZ];   // 128 MB
__device__ float g_xp2[(size_t)M_SZ * O_SZ];   //  64 MB

// ---------------------------------------------------------------------------
union f2u { float2 f; unsigned long long u; };

__device__ __forceinline__ float2 ffma2(float2 a, float2 b, float2 c) {
    f2u A, Bv, C;
    A.f = a; Bv.f = b; C.f = c;
    asm("fma.rn.f32x2 %0, %1, %2, %3;"
        : "=l"(C.u) : "l"(A.u), "l"(Bv.u), "l"(C.u));
    return C.f;
}

// Branch-free fast tanh (validated: rel_err 4.4e-7 vs 1e-3 budget)
__device__ __forceinline__ float fast_tanh(float x) {
    float ax = fabsf(x);
    float e  = __expf(-2.0f * ax);
    float t  = __fdividef(1.0f - e, 1.0f + e);
    return copysignf(t, x);
}

__device__ __forceinline__ uint32_t smem_u32(const void* p) {
    return (uint32_t)__cvta_generic_to_shared(p);
}
__device__ __forceinline__ uint32_t mapa_peer(uint32_t a, unsigned peer) {
    uint32_t r;
    asm("mapa.shared::cluster.u32 %0, %1, %2;" : "=r"(r) : "r"(a), "r"(peer));
    return r;
}
__device__ __forceinline__ void mbar_wait_acq_cluster(uint32_t mbar, uint32_t parity) {
    asm volatile(
        "{\n\t.reg .pred P;\n\t"
        "W_%=:\n\t"
        "mbarrier.try_wait.parity.acquire.cluster.shared::cta.b64 P, [%0], %1;\n\t"
        "@!P bra W_%=;\n\t}"
        :: "r"(mbar), "r"(parity) : "memory");
}

// ---------------------------------------------------------------------------
// SGEMM with fused double-bias (frozen since R5)
// ---------------------------------------------------------------------------
__global__ __launch_bounds__(256, 2)
void sgemm_bias_kernel(const float* __restrict__ A,
                       const float* __restrict__ W,
                       const float* __restrict__ bias_a,
                       const float* __restrict__ bias_b,
                       float* __restrict__ C, int K, int N)
{
    constexpr int BM = 128, BN = 128, BK = 16;
    __shared__ float As[BK][BM];
    __shared__ float Bs[BK][BN];

    int tid = threadIdx.x;
    int bm = blockIdx.y * BM;
    int bn = blockIdx.x * BN;
    int tm = tid >> 4;
    int tn = tid & 15;

    float2 acc[8][4];
    #pragma unroll
    for (int i = 0; i < 8; i++)
        #pragma unroll
        for (int j = 0; j < 4; j++) acc[i][j] = make_float2(0.f, 0.f);

    const float* Ab = A + (size_t)bm * K;
    const float* Wb = W + (size_t)bn * K;

    for (int kt = 0; kt < K; kt += BK) {
        #pragma unroll
        for (int it = 0; it < 2; it++) {
            int lid = tid * 2 + it;
            int row = lid >> 2, c4 = lid & 3;
            float4 v = *(const float4*)(Ab + (size_t)row * K + kt + c4 * 4);
            As[c4 * 4 + 0][row] = v.x;
            As[c4 * 4 + 1][row] = v.y;
            As[c4 * 4 + 2][row] = v.z;
            As[c4 * 4 + 3][row] = v.w;
        }
        #pragma unroll
        for (int it = 0; it < 2; it++) {
            int lid = tid * 2 + it;
            int row = lid >> 2, c4 = lid & 3;
            float4 v = *(const float4*)(Wb + (size_t)row * K + kt + c4 * 4);
            Bs[c4 * 4 + 0][row] = v.x;
            Bs[c4 * 4 + 1][row] = v.y;
            Bs[c4 * 4 + 2][row] = v.z;
            Bs[c4 * 4 + 3][row] = v.w;
        }
        __syncthreads();

        #pragma unroll
        for (int kk = 0; kk < BK; kk++) {
            float4 a0 = *(const float4*)&As[kk][tm * 8];
            float4 a1 = *(const float4*)&As[kk][tm * 8 + 4];
            float4 b0 = *(const float4*)&Bs[kk][tn * 8];
            float4 b1 = *(const float4*)&Bs[kk][tn * 8 + 4];
            float av[8] = {a0.x, a0.y, a0.z, a0.w, a1.x, a1.y, a1.z, a1.w};
            float2 bv[4] = {make_float2(b0.x, b0.y), make_float2(b0.z, b0.w),
                            make_float2(b1.x, b1.y), make_float2(b1.z, b1.w)};
            #pragma unroll
            for (int i = 0; i < 8; i++) {
                float2 ai = make_float2(av[i], av[i]);
                #pragma unroll
                for (int j = 0; j < 4; j++)
                    acc[i][j] = ffma2(ai, bv[j], acc[i][j]);
            }
        }
        __syncthreads();
    }

    float2 bb[4];
    #pragma unroll
    for (int j = 0; j < 4; j++) {
        int n = bn + tn * 8 + j * 2;
        bb[j] = make_float2(bias_a[n] + bias_b[n], bias_a[n + 1] + bias_b[n + 1]);
    }
    #pragma unroll
    for (int i = 0; i < 8; i++) {
        int m = bm + tm * 8 + i;
        float* Crow = C + (size_t)m * N + bn + tn * 8;
        #pragma unroll
        for (int j = 0; j < 4; j++) {
            float2 v = make_float2(acc[i][j].x + bb[j].x, acc[i][j].y + bb[j].y);
            *(float2*)(Crow + j * 2) = v;
        }
    }
}

// ---------------------------------------------------------------------------
// Layer-1 scan, cluster-2 per batch. R6 protocol with ONE reorder:
// the DSMEM store + release-arrive now happen AFTER __syncthreads, so the
// barrier no longer drains the remote STS through the fabric (BAR.SYNC drains
// pending STS — B300 measured). Arrive is per storing lane (count=128/phase),
// still strictly after all local reads of hbuf[p] (sync precedes it), so the
// anti-overwrite guarantee is unchanged.
// ---------------------------------------------------------------------------
__global__ void __cluster_dims__(2, 1, 1) __launch_bounds__(512, 1)
rnn_scan1_kernel(const float* __restrict__ W_hh,
                 const float* __restrict__ xp,
                 float* __restrict__ h1out)
{
    __shared__ float hbuf[2][4 * 68];
    __shared__ alignas(8) unsigned long long mbar;

    int tid = threadIdx.x;
    int o_local = tid >> 2;     // 0..127
    int c = tid & 3;            // input chunk 0..3 (64 inputs each)
    unsigned r;
    asm("mov.u32 %0, %%cluster_ctarank;" : "=r"(r));
    int b = blockIdx.x >> 1;
    int o_global = (int)r * 128 + o_local;

    float2 w2[32];
    {
        const float4* wp = (const float4*)(W_hh + (size_t)o_global * H_SZ + c * 64);
        #pragma unroll
        for (int j = 0; j < 16; j++) {
            int jj = (j + c * 4) & 15;
            float4 v = wp[jj];
            w2[2 * j]     = make_float2(v.x, v.y);
            w2[2 * j + 1] = make_float2(v.z, v.w);
        }
    }

    if (tid < 256) hbuf[0][(tid >> 6) * 68 + (tid & 63)] = 0.f;   // h0 = 0

    uint32_t mb = smem_u32(&mbar);
    if (tid == 0)   // 128 arrivals per phase (one per storing lane)
        asm volatile("mbarrier.init.shared.b64 [%0], %1;" :: "r"(mb), "r"(128) : "memory");

    int wpos = (o_global >> 6) * 68 + (o_global & 63);
    uint32_t l0 = smem_u32(&hbuf[0][wpos]);
    uint32_t l1 = smem_u32(&hbuf[1][wpos]);
    unsigned peer = r ^ 1u;
    uint32_t rem0 = mapa_peer(l0, peer);
    uint32_t rem1 = mapa_peer(l1, peer);
    uint32_t rmb  = mapa_peer(mb, peer);

    const float* xpb = xp + (size_t)b * T_SZ * H_SZ + o_global;
    float* hob = h1out + (size_t)b * T_SZ * H_SZ + o_global;

    float pf[4];
    #pragma unroll
    for (int i = 0; i < 4; i++)
        pf[i] = __ldg(xpb + (size_t)i * H_SZ);

    // mbar + h0 visible cluster-wide before any remote traffic
    asm volatile("barrier.cluster.arrive.aligned;\n\tbarrier.cluster.wait.aligned;" ::: "memory");

    int p = 0;
    #pragma unroll 4
    for (int t = 0; t < T_SZ; t++) {
        // Peer half of h_t arrived? (phase t-1). Local half: previous sync.
        if (t > 0)
            mbar_wait_acq_cluster(mb, (uint32_t)((t - 1) & 1));

        float xv = pf[t & 3];
        int tn4 = (t + 4 < T_SZ) ? (t + 4) : (T_SZ - 1);
        pf[t & 3] = __ldg(xpb + (size_t)tn4 * H_SZ);

        const float* hb = &hbuf[p][c * 68];
        float2 a0 = make_float2(0.f, 0.f), a1 = a0, a2 = a0, a3 = a0;
        #pragma unroll
        for (int j = 0; j < 16; j++) {
            int jj = (j + c * 4) & 15;                     // bank-decorrelating rotation
            float4 hv = *(const float4*)(hb + jj * 4);
            float2 h01 = make_float2(hv.x, hv.y);
            float2 h23 = make_float2(hv.z, hv.w);
            if (j & 1) { a2 = ffma2(h01, w2[2 * j], a2); a3 = ffma2(h23, w2[2 * j + 1], a3); }
            else       { a0 = ffma2(h01, w2[2 * j], a0); a1 = ffma2(h23, w2[2 * j + 1], a1); }
        }
        float2 s2 = make_float2(a0.x + a1.x + a2.x + a3.x, a0.y + a1.y + a2.y + a3.y);
        float s = s2.x + s2.y;
        s += __shfl_xor_sync(0xffffffffu, s, 1);
        s += __shfl_xor_sync(0xffffffffu, s, 2);

        float v = fast_tanh(s + xv);                       // all lanes, branch-free
        hbuf[p ^ 1][wpos] = v;                             // LOCAL store only (merged)

        __syncthreads();                                   // drains local STS; reads done

        if (c == 0) {                                      // remote traffic AFTER the BAR
            uint32_t ra = p ? rem0 : rem1;                 // peer copy (buffer p^1)
            asm volatile("st.shared::cluster.f32 [%0], %1;" :: "r"(ra), "f"(v) : "memory");
            asm volatile("mbarrier.arrive.release.cluster.shared::cluster.b64 _, [%0];"
                         :: "r"(rmb) : "memory");          // orders this lane's store
            hob[(size_t)t * H_SZ] = v;                     // h1 for layer-2 GEMM
        }
        p ^= 1;
    }

    // keep SMEM alive until peer's last remote ops land
    asm volatile("barrier.cluster.arrive.aligned;\n\tbarrier.cluster.wait.aligned;" ::: "memory");
}

// ---------------------------------------------------------------------------
// Layer-2 scan: one CTA of 256 threads per batch. o=tid>>1 (output), c=tid&1
// (64-input chunk). Half the warps of R6 -> cheaper BAR, single-shfl reduce,
// 2-address broadcast LDS (conflict-free, no rotation needed).
// ---------------------------------------------------------------------------
__global__ __launch_bounds__(256, 1)
void rnn_scan2_kernel(const float* __restrict__ W_hh,
                      const float* __restrict__ xp,
                      float* __restrict__ out)
{
    __shared__ float obuf[2][2 * 68];

    int tid = threadIdx.x;
    int o = tid >> 1;           // 0..127
    int c = tid & 1;            // 64 inputs each
    int b = blockIdx.x;

    float2 w2[32];
    {
        const float4* wp = (const float4*)(W_hh + (size_t)o * O_SZ + c * 64);
        #pragma unroll
        for (int j = 0; j < 16; j++) {
            float4 v = wp[j];
            w2[2 * j]     = make_float2(v.x, v.y);
            w2[2 * j + 1] = make_float2(v.z, v.w);
        }
    }

    if (tid < 128) obuf[0][(tid >> 6) * 68 + (tid & 63)] = 0.f;
    int wpos = (o >> 6) * 68 + (o & 63);

    const float* xpb = xp + (size_t)b * T_SZ * O_SZ + o;
    float* ob = out + (size_t)b * T_SZ * O_SZ + o;

    float pf[4];
    #pragma unroll
    for (int i = 0; i < 4; i++)
        pf[i] = __ldg(xpb + (size_t)i * O_SZ);

    __syncthreads();

    int p = 0;
    #pragma unroll 2
    for (int t = 0; t < T_SZ; t++) {
        float xv = pf[t & 3];
        int tn4 = (t + 4 < T_SZ) ? (t + 4) : (T_SZ - 1);
        pf[t & 3] = __ldg(xpb + (size_t)tn4 * O_SZ);

        const float4* hb = (const float4*)&obuf[p][c * 68];
        float2 a0 = make_float2(0.f, 0.f), a1 = a0, a2 = a0, a3 = a0;
        #pragma unroll
        for (int j = 0; j < 8; j++) {
            float4 h0 = hb[2 * j];
            float4 h1v = hb[2 * j + 1];
            a0 = ffma2(make_float2(h0.x,  h0.y),  w2[4 * j],     a0);
            a1 = ffma2(make_float2(h0.z,  h0.w),  w2[4 * j + 1], a1);
            a2 = ffma2(make_float2(h1v.x, h1v.y), w2[4 * j + 2], a2);
            a3 = ffma2(make_float2(h1v.z, h1v.w), w2[4 * j + 3], a3);
        }
        float s = (a0.x + a1.x) + (a2.x + a3.x) + (a0.y + a1.y) + (a2.y + a3.y);
        s += __shfl_xor_sync(0xffffffffu, s, 1);           // both lanes get total

        float v = fast_tanh(s + xv);                       // both lanes, branch-free
        obuf[p ^ 1][wpos] = v;                             // 2-way write-merge
        ob[(size_t)t * O_SZ] = v;                          // final output (merged)
        __syncthreads();
        p ^= 1;
    }
}

// ---------------------------------------------------------------------------
extern "C" void kernel_launch(void* const* d_in, const int* in_sizes, int n_in,
                              void* d_out, int out_size)
{
    const float* x     = (const float*)d_in[0];
    const float* W_ih1 = (const float*)d_in[1];
    const float* W_hh1 = (const float*)d_in[2];
    const float* b_ih1 = (const float*)d_in[3];
    const float* b_hh1 = (const float*)d_in[4];
    const float* W_ih2 = (const float*)d_in[5];
    const float* W_hh2 = (const float*)d_in[6];
    const float* b_ih2 = (const float*)d_in[7];
    const float* b_hh2 = (const float*)d_in[8];
    float* out = (float*)d_out;

    float *xp1, *h1, *xp2;
    cudaGetSymbolAddress((void**)&xp1, g_xp1);
    cudaGetSymbolAddress((void**)&h1,  g_h1);
    cudaGetSymbolAddress((void**)&xp2, g_xp2);

    // Phase 1: xp1 = x @ W_ih1^T + (b_ih1 + b_hh1)   [131072 x 256]
    dim3 g1(H_SZ / 128, M_SZ / 128);
    sgemm_bias_kernel<<<g1, 256>>>(x, W_ih1, b_ih1, b_hh1, xp1, I_SZ, H_SZ);

    // Phase 2: layer-1 recurrent scan (cluster-2 per batch), emits h1
    rnn_scan1_kernel<<<B_SZ * 2, 512>>>(W_hh1, xp1, h1);

    // Phase 3: xp2 = h1 @ W_ih2^T + (b_ih2 + b_hh2)  [131072 x 128]
    dim3 g2(O_SZ / 128, M_SZ / 128);
    sgemm_bias_kernel<<<g2, 256>>>(h1, W_ih2, b_ih2, b_hh2, xp2, H_SZ, O_SZ);

    // Phase 4: layer-2 recurrent scan, writes final output
    rnn_scan2_kernel<<<B_SZ, 256>>>(W_hh2, xp2, out);
}

// round 9
// speedup vs baseline: 1.8660x; 1.2364x over previous
#include <cuda_runtime.h>
#include <cstdint>

#define B_SZ 64
#define T_SZ 2048
#define I_SZ 256
#define H_SZ 256
#define O_SZ 128
#define M_SZ (B_SZ * T_SZ)   // 131072 rows

// Scratch (device globals: no allocations allowed)
__device__ float g_xp1[(size_t)M_SZ * H_SZ];   // 128 MB
__device__ float g_h1 [(size_t)M_SZ * H_SZ];   // 128 MB
__device__ float g_xp2[(size_t)M_SZ * O_SZ];   //  64 MB

// ---------------------------------------------------------------------------
union f2u { float2 f; unsigned long long u; };

__device__ __forceinline__ float2 ffma2(float2 a, float2 b, float2 c) {
    f2u A, Bv, C;
    A.f = a; Bv.f = b; C.f = c;
    asm("fma.rn.f32x2 %0, %1, %2, %3;"
        : "=l"(C.u) : "l"(A.u), "l"(Bv.u), "l"(C.u));
    return C.f;
}

// Branch-free fast tanh (validated: rel_err 4.4e-7 vs 1e-3 budget)
__device__ __forceinline__ float fast_tanh(float x) {
    float ax = fabsf(x);
    float e  = __expf(-2.0f * ax);
    float t  = __fdividef(1.0f - e, 1.0f + e);
    return copysignf(t, x);
}

__device__ __forceinline__ uint32_t smem_u32(const void* p) {
    return (uint32_t)__cvta_generic_to_shared(p);
}
__device__ __forceinline__ uint32_t mapa_peer(uint32_t a, unsigned peer) {
    uint32_t r;
    asm("mapa.shared::cluster.u32 %0, %1, %2;" : "=r"(r) : "r"(a), "r"(peer));
    return r;
}
__device__ __forceinline__ void mbar_wait_acq_cluster(uint32_t mbar, uint32_t parity) {
    asm volatile(
        "{\n\t.reg .pred P;\n\t"
        "W_%=:\n\t"
        "mbarrier.try_wait.parity.acquire.cluster.shared::cta.b64 P, [%0], %1;\n\t"
        "@!P bra W_%=;\n\t}"
        :: "r"(mbar), "r"(parity) : "memory");
}

// ---------------------------------------------------------------------------
// SGEMM with fused double-bias (frozen since R5)
// ---------------------------------------------------------------------------
__global__ __launch_bounds__(256, 2)
void sgemm_bias_kernel(const float* __restrict__ A,
                       const float* __restrict__ W,
                       const float* __restrict__ bias_a,
                       const float* __restrict__ bias_b,
                       float* __restrict__ C, int K, int N)
{
    constexpr int BM = 128, BN = 128, BK = 16;
    __shared__ float As[BK][BM];
    __shared__ float Bs[BK][BN];

    int tid = threadIdx.x;
    int bm = blockIdx.y * BM;
    int bn = blockIdx.x * BN;
    int tm = tid >> 4;
    int tn = tid & 15;

    float2 acc[8][4];
    #pragma unroll
    for (int i = 0; i < 8; i++)
        #pragma unroll
        for (int j = 0; j < 4; j++) acc[i][j] = make_float2(0.f, 0.f);

    const float* Ab = A + (size_t)bm * K;
    const float* Wb = W + (size_t)bn * K;

    for (int kt = 0; kt < K; kt += BK) {
        #pragma unroll
        for (int it = 0; it < 2; it++) {
            int lid = tid * 2 + it;
            int row = lid >> 2, c4 = lid & 3;
            float4 v = *(const float4*)(Ab + (size_t)row * K + kt + c4 * 4);
            As[c4 * 4 + 0][row] = v.x;
            As[c4 * 4 + 1][row] = v.y;
            As[c4 * 4 + 2][row] = v.z;
            As[c4 * 4 + 3][row] = v.w;
        }
        #pragma unroll
        for (int it = 0; it < 2; it++) {
            int lid = tid * 2 + it;
            int row = lid >> 2, c4 = lid & 3;
            float4 v = *(const float4*)(Wb + (size_t)row * K + kt + c4 * 4);
            Bs[c4 * 4 + 0][row] = v.x;
            Bs[c4 * 4 + 1][row] = v.y;
            Bs[c4 * 4 + 2][row] = v.z;
            Bs[c4 * 4 + 3][row] = v.w;
        }
        __syncthreads();

        #pragma unroll
        for (int kk = 0; kk < BK; kk++) {
            float4 a0 = *(const float4*)&As[kk][tm * 8];
            float4 a1 = *(const float4*)&As[kk][tm * 8 + 4];
            float4 b0 = *(const float4*)&Bs[kk][tn * 8];
            float4 b1 = *(const float4*)&Bs[kk][tn * 8 + 4];
            float av[8] = {a0.x, a0.y, a0.z, a0.w, a1.x, a1.y, a1.z, a1.w};
            float2 bv[4] = {make_float2(b0.x, b0.y), make_float2(b0.z, b0.w),
                            make_float2(b1.x, b1.y), make_float2(b1.z, b1.w)};
            #pragma unroll
            for (int i = 0; i < 8; i++) {
                float2 ai = make_float2(av[i], av[i]);
                #pragma unroll
                for (int j = 0; j < 4; j++)
                    acc[i][j] = ffma2(ai, bv[j], acc[i][j]);
            }
        }
        __syncthreads();
    }

    float2 bb[4];
    #pragma unroll
    for (int j = 0; j < 4; j++) {
        int n = bn + tn * 8 + j * 2;
        bb[j] = make_float2(bias_a[n] + bias_b[n], bias_a[n + 1] + bias_b[n + 1]);
    }
    #pragma unroll
    for (int i = 0; i < 8; i++) {
        int m = bm + tm * 8 + i;
        float* Crow = C + (size_t)m * N + bn + tn * 8;
        #pragma unroll
        for (int j = 0; j < 4; j++) {
            float2 v = make_float2(acc[i][j].x + bb[j].x, acc[i][j].y + bb[j].y);
            *(float2*)(Crow + j * 2) = v;
        }
    }
}

// ---------------------------------------------------------------------------
// Layer-1 scan: cluster-2 per batch, 256 threads/CTA.
//   o = tid>>1 (output row, 128 per CTA), c = tid&1 (128-input half).
// 128 weights per thread in registers; single shfl reduce; one STS per output;
// DSMEM store + release-arrive after the barrier (R8 protocol, mbar count=128).
// ---------------------------------------------------------------------------
__global__ void __cluster_dims__(2, 1, 1) __launch_bounds__(256, 1)
rnn_scan1_kernel(const float* __restrict__ W_hh,
                 const float* __restrict__ xp,
                 float* __restrict__ h1out)
{
    __shared__ float hbuf[2][4 * 68];      // 4 chunks of 64 floats, stride 68
    __shared__ alignas(8) unsigned long long mbar;

    int tid = threadIdx.x;
    int o_local = tid >> 1;     // 0..127
    int c = tid & 1;            // input half 0..1 (128 inputs each)
    unsigned r;
    asm("mov.u32 %0, %%cluster_ctarank;" : "=r"(r));
    int b = blockIdx.x >> 1;
    int o_global = (int)r * 128 + o_local;

    // 128 register-resident weights (64 f32x2) per thread
    float2 w2[64];
    {
        const float4* wp = (const float4*)(W_hh + (size_t)o_global * H_SZ + c * 128);
        #pragma unroll
        for (int j = 0; j < 32; j++) {
            float4 v = wp[j];
            w2[2 * j]     = make_float2(v.x, v.y);
            w2[2 * j + 1] = make_float2(v.z, v.w);
        }
    }

    if (tid < 256) hbuf[0][(tid >> 6) * 68 + (tid & 63)] = 0.f;   // h0 = 0

    uint32_t mb = smem_u32(&mbar);
    if (tid == 0)   // 128 arrivals per phase (one per storing lane)
        asm volatile("mbarrier.init.shared.b64 [%0], %1;" :: "r"(mb), "r"(128) : "memory");

    int wpos = (o_global >> 6) * 68 + (o_global & 63);
    uint32_t l0 = smem_u32(&hbuf[0][wpos]);
    uint32_t l1 = smem_u32(&hbuf[1][wpos]);
    unsigned peer = r ^ 1u;
    uint32_t rem0 = mapa_peer(l0, peer);
    uint32_t rem1 = mapa_peer(l1, peer);
    uint32_t rmb  = mapa_peer(mb, peer);

    const float* xpb = xp + (size_t)b * T_SZ * H_SZ + o_global;
    float* hob = h1out + (size_t)b * T_SZ * H_SZ + o_global;

    float pf[4];
    #pragma unroll
    for (int i = 0; i < 4; i++)
        pf[i] = __ldg(xpb + (size_t)i * H_SZ);

    // mbar + h0 visible cluster-wide before any remote traffic
    asm volatile("barrier.cluster.arrive.aligned;\n\tbarrier.cluster.wait.aligned;" ::: "memory");

    int p = 0;
    #pragma unroll 4
    for (int t = 0; t < T_SZ; t++) {
        if (t > 0)
            mbar_wait_acq_cluster(mb, (uint32_t)((t - 1) & 1));

        float xv = pf[t & 3];
        int tn4 = (t + 4 < T_SZ) ? (t + 4) : (T_SZ - 1);
        pf[t & 3] = __ldg(xpb + (size_t)tn4 * H_SZ);

        // c selects 2 chunks of 64 (chunk ids 2c, 2c+1); stride-68 keeps the
        // two warp addresses on different banks (offset diff 68*2 mod 32 != 0).
        const float* hb = &hbuf[p][(2 * c) * 68];
        float2 a0 = make_float2(0.f, 0.f), a1 = a0, a2 = a0, a3 = a0;
        #pragma unroll
        for (int half = 0; half < 2; half++) {
            const float4* hq = (const float4*)(hb + half * 68);
            #pragma unroll
            for (int j = 0; j < 8; j++) {
                float4 h0 = hq[2 * j];
                float4 h1v = hq[2 * j + 1];
                int base = half * 32 + 4 * j;
                a0 = ffma2(make_float2(h0.x,  h0.y),  w2[base],     a0);
                a1 = ffma2(make_float2(h0.z,  h0.w),  w2[base + 1], a1);
                a2 = ffma2(make_float2(h1v.x, h1v.y), w2[base + 2], a2);
                a3 = ffma2(make_float2(h1v.z, h1v.w), w2[base + 3], a3);
            }
        }
        float s = (a0.x + a1.x) + (a2.x + a3.x) + (a0.y + a1.y) + (a2.y + a3.y);
        s += __shfl_xor_sync(0xffffffffu, s, 1);           // single shfl: pair total

        float v = fast_tanh(s + xv);
        if (c == 0)
            hbuf[p ^ 1][wpos] = v;                         // ONE local STS per output

        __syncthreads();                                   // reads of hbuf[p] done

        if (c == 0) {                                      // remote traffic after BAR
            uint32_t ra = p ? rem0 : rem1;
            asm volatile("st.shared::cluster.f32 [%0], %1;" :: "r"(ra), "f"(v) : "memory");
            asm volatile("mbarrier.arrive.release.cluster.shared::cluster.b64 _, [%0];"
                         :: "r"(rmb) : "memory");
            hob[(size_t)t * H_SZ] = v;                     // h1 for layer-2 GEMM
        }
        p ^= 1;
    }

    asm volatile("barrier.cluster.arrive.aligned;\n\tbarrier.cluster.wait.aligned;" ::: "memory");
}

// ---------------------------------------------------------------------------
// Layer-2 scan: one CTA of 128 threads per batch; thread == output.
// All 128 weights in registers, NO reduction, one STS + one STG per step.
// LDS reads are pure warp-broadcasts (all lanes same address).
// ---------------------------------------------------------------------------
__global__ __launch_bounds__(128, 1)
void rnn_scan2_kernel(const float* __restrict__ W_hh,
                      const float* __restrict__ xp,
                      float* __restrict__ out)
{
    __shared__ float obuf[2][O_SZ];

    int tid = threadIdx.x;      // == output index o
    int b = blockIdx.x;

    float2 w2[64];
    {
        const float4* wp = (const float4*)(W_hh + (size_t)tid * O_SZ);
        #pragma unroll
        for (int j = 0; j < 32; j++) {
            float4 v = wp[j];
            w2[2 * j]     = make_float2(v.x, v.y);
            w2[2 * j + 1] = make_float2(v.z, v.w);
        }
    }

    obuf[0][tid] = 0.f;

    const float* xpb = xp + (size_t)b * T_SZ * O_SZ + tid;
    float* ob = out + (size_t)b * T_SZ * O_SZ + tid;

    float pf[4];
    #pragma unroll
    for (int i = 0; i < 4; i++)
        pf[i] = __ldg(xpb + (size_t)i * O_SZ);

    __syncthreads();

    int p = 0;
    #pragma unroll 4
    for (int t = 0; t < T_SZ; t++) {
        float xv = pf[t & 3];
        int tn4 = (t + 4 < T_SZ) ? (t + 4) : (T_SZ - 1);
        pf[t & 3] = __ldg(xpb + (size_t)tn4 * O_SZ);

        const float4* hb = (const float4*)&obuf[p][0];     // warp-broadcast reads
        float2 a0 = make_float2(0.f, 0.f), a1 = a0, a2 = a0, a3 = a0;
        #pragma unroll
        for (int j = 0; j < 8; j++) {
            float4 h0 = hb[4 * j];
            float4 h1v = hb[4 * j + 1];
            float4 h2 = hb[4 * j + 2];
            float4 h3 = hb[4 * j + 3];
            a0 = ffma2(make_float2(h0.x,  h0.y),  w2[8 * j],     a0);
            a1 = ffma2(make_float2(h0.z,  h0.w),  w2[8 * j + 1], a1);
            a2 = ffma2(make_float2(h1v.x, h1v.y), w2[8 * j + 2], a2);
            a3 = ffma2(make_float2(h1v.z, h1v.w), w2[8 * j + 3], a3);
            a0 = ffma2(make_float2(h2.x,  h2.y),  w2[8 * j + 4], a0);
            a1 = ffma2(make_float2(h2.z,  h2.w),  w2[8 * j + 5], a1);
            a2 = ffma2(make_float2(h3.x,  h3.y),  w2[8 * j + 6], a2);
            a3 = ffma2(make_float2(h3.z,  h3.w),  w2[8 * j + 7], a3);
        }
        float s = (a0.x + a1.x) + (a2.x + a3.x) + (a0.y + a1.y) + (a2.y + a3.y);

        float v = fast_tanh(s + xv);                       // no reduction needed
        obuf[p ^ 1][tid] = v;                              // ONE STS
        ob[(size_t)t * O_SZ] = v;                          // ONE STG
        __syncthreads();
        p ^= 1;
    }
}

// ---------------------------------------------------------------------------
extern "C" void kernel_launch(void* const* d_in, const int* in_sizes, int n_in,
                              void* d_out, int out_size)
{
    const float* x     = (const float*)d_in[0];
    const float* W_ih1 = (const float*)d_in[1];
    const float* W_hh1 = (const float*)d_in[2];
    const float* b_ih1 = (const float*)d_in[3];
    const float* b_hh1 = (const float*)d_in[4];
    const float* W_ih2 = (const float*)d_in[5];
    const float* W_hh2 = (const float*)d_in[6];
    const float* b_ih2 = (const float*)d_in[7];
    const float* b_hh2 = (const float*)d_in[8];
    float* out = (float*)d_out;

    float *xp1, *h1, *xp2;
    cudaGetSymbolAddress((void**)&xp1, g_xp1);
    cudaGetSymbolAddress((void**)&h1,  g_h1);
    cudaGetSymbolAddress((void**)&xp2, g_xp2);

    // Phase 1: xp1 = x @ W_ih1^T + (b_ih1 + b_hh1)   [131072 x 256]
    dim3 g1(H_SZ / 128, M_SZ / 128);
    sgemm_bias_kernel<<<g1, 256>>>(x, W_ih1, b_ih1, b_hh1, xp1, I_SZ, H_SZ);

    // Phase 2: layer-1 recurrent scan (cluster-2 per batch), emits h1
    rnn_scan1_kernel<<<B_SZ * 2, 256>>>(W_hh1, xp1, h1);

    // Phase 3: xp2 = h1 @ W_ih2^T + (b_ih2 + b_hh2)  [131072 x 128]
    dim3 g2(O_SZ / 128, M_SZ / 128);
    sgemm_bias_kernel<<<g2, 256>>>(h1, W_ih2, b_ih2, b_hh2, xp2, H_SZ, O_SZ);

    // Phase 4: layer-2 recurrent scan, writes final output
    rnn_scan2_kernel<<<B_SZ, 128>>>(W_hh2, xp2, out);
}

// round 10
// speedup vs baseline: 2.0189x; 1.0819x over previous
#include <cuda_runtime.h>
#include <cstdint>

#define B_SZ 64
#define T_SZ 2048
#define I_SZ 256
#define H_SZ 256
#define O_SZ 128
#define M_SZ (B_SZ * T_SZ)   // 131072 rows

// Scratch (device globals: no allocations allowed)
__device__ float g_xp1[(size_t)M_SZ * H_SZ];   // 128 MB
__device__ float g_h1 [(size_t)M_SZ * H_SZ];   // 128 MB
__device__ float g_xp2[(size_t)M_SZ * O_SZ];   //  64 MB

// ---------------------------------------------------------------------------
union f2u { float2 f; unsigned long long u; };

__device__ __forceinline__ float2 ffma2(float2 a, float2 b, float2 c) {
    f2u A, Bv, C;
    A.f = a; Bv.f = b; C.f = c;
    asm("fma.rn.f32x2 %0, %1, %2, %3;"
        : "=l"(C.u) : "l"(A.u), "l"(Bv.u), "l"(C.u));
    return C.f;
}

// Branch-free fast tanh (validated: rel_err 4.4e-7 vs 1e-3 budget)
__device__ __forceinline__ float fast_tanh(float x) {
    float ax = fabsf(x);
    float e  = __expf(-2.0f * ax);
    float t  = __fdividef(1.0f - e, 1.0f + e);
    return copysignf(t, x);
}

__device__ __forceinline__ uint32_t smem_u32(const void* p) {
    return (uint32_t)__cvta_generic_to_shared(p);
}
__device__ __forceinline__ uint32_t mapa_peer(uint32_t a, unsigned peer) {
    uint32_t r;
    asm("mapa.shared::cluster.u32 %0, %1, %2;" : "=r"(r) : "r"(a), "r"(peer));
    return r;
}
__device__ __forceinline__ void mbar_wait_acq_cluster(uint32_t mbar, uint32_t parity) {
    asm volatile(
        "{\n\t.reg .pred P;\n\t"
        "W_%=:\n\t"
        "mbarrier.try_wait.parity.acquire.cluster.shared::cta.b64 P, [%0], %1;\n\t"
        "@!P bra W_%=;\n\t}"
        :: "r"(mbar), "r"(parity) : "memory");
}

// ---------------------------------------------------------------------------
// SGEMM with fused double-bias (frozen since R5)
// ---------------------------------------------------------------------------
__global__ __launch_bounds__(256, 2)
void sgemm_bias_kernel(const float* __restrict__ A,
                       const float* __restrict__ W,
                       const float* __restrict__ bias_a,
                       const float* __restrict__ bias_b,
                       float* __restrict__ C, int K, int N)
{
    constexpr int BM = 128, BN = 128, BK = 16;
    __shared__ float As[BK][BM];
    __shared__ float Bs[BK][BN];

    int tid = threadIdx.x;
    int bm = blockIdx.y * BM;
    int bn = blockIdx.x * BN;
    int tm = tid >> 4;
    int tn = tid & 15;

    float2 acc[8][4];
    #pragma unroll
    for (int i = 0; i < 8; i++)
        #pragma unroll
        for (int j = 0; j < 4; j++) acc[i][j] = make_float2(0.f, 0.f);

    const float* Ab = A + (size_t)bm * K;
    const float* Wb = W + (size_t)bn * K;

    for (int kt = 0; kt < K; kt += BK) {
        #pragma unroll
        for (int it = 0; it < 2; it++) {
            int lid = tid * 2 + it;
            int row = lid >> 2, c4 = lid & 3;
            float4 v = *(const float4*)(Ab + (size_t)row * K + kt + c4 * 4);
            As[c4 * 4 + 0][row] = v.x;
            As[c4 * 4 + 1][row] = v.y;
            As[c4 * 4 + 2][row] = v.z;
            As[c4 * 4 + 3][row] = v.w;
        }
        #pragma unroll
        for (int it = 0; it < 2; it++) {
            int lid = tid * 2 + it;
            int row = lid >> 2, c4 = lid & 3;
            float4 v = *(const float4*)(Wb + (size_t)row * K + kt + c4 * 4);
            Bs[c4 * 4 + 0][row] = v.x;
            Bs[c4 * 4 + 1][row] = v.y;
            Bs[c4 * 4 + 2][row] = v.z;
            Bs[c4 * 4 + 3][row] = v.w;
        }
        __syncthreads();

        #pragma unroll
        for (int kk = 0; kk < BK; kk++) {
            float4 a0 = *(const float4*)&As[kk][tm * 8];
            float4 a1 = *(const float4*)&As[kk][tm * 8 + 4];
            float4 b0 = *(const float4*)&Bs[kk][tn * 8];
            float4 b1 = *(const float4*)&Bs[kk][tn * 8 + 4];
            float av[8] = {a0.x, a0.y, a0.z, a0.w, a1.x, a1.y, a1.z, a1.w};
            float2 bv[4] = {make_float2(b0.x, b0.y), make_float2(b0.z, b0.w),
                            make_float2(b1.x, b1.y), make_float2(b1.z, b1.w)};
            #pragma unroll
            for (int i = 0; i < 8; i++) {
                float2 ai = make_float2(av[i], av[i]);
                #pragma unroll
                for (int j = 0; j < 4; j++)
                    acc[i][j] = ffma2(ai, bv[j], acc[i][j]);
            }
        }
        __syncthreads();
    }

    float2 bb[4];
    #pragma unroll
    for (int j = 0; j < 4; j++) {
        int n = bn + tn * 8 + j * 2;
        bb[j] = make_float2(bias_a[n] + bias_b[n], bias_a[n + 1] + bias_b[n + 1]);
    }
    #pragma unroll
    for (int i = 0; i < 8; i++) {
        int m = bm + tm * 8 + i;
        float* Crow = C + (size_t)m * N + bn + tn * 8;
        #pragma unroll
        for (int j = 0; j < 4; j++) {
            float2 v = make_float2(acc[i][j].x + bb[j].x, acc[i][j].y + bb[j].y);
            *(float2*)(Crow + j * 2) = v;
        }
    }
}

// ---------------------------------------------------------------------------
// Layer-1 scan: cluster-2 per batch, 256 threads/CTA, PSUM EXCHANGE.
// CTA r holds, for ALL 256 outputs, the weight columns of ITS input half
// (thread tid = output o, 128 weights in regs). Per step:
//   FMA over LOCAL h half only (no wait in front!)
//   o-in-peer-half threads: st.shared::cluster psum -> peer pbuf + arrive
//   all: wait mbar (late), owners: tanh(own + peer psum + xp), write local h
//   one __syncthreads.
// Max skew between CTAs is 1 step (peer's next FMA needs my psums), so the
// double-buffered pbuf/hbuf cannot be clobbered early.
// ---------------------------------------------------------------------------
__global__ void __cluster_dims__(2, 1, 1) __launch_bounds__(256, 1)
rnn_scan1_kernel(const float* __restrict__ W_hh,
                 const float* __restrict__ xp,
                 float* __restrict__ h1out)
{
    __shared__ alignas(16) float hbuf[2][128];   // local h half, double-buffered
    __shared__ alignas(16) float pbuf[2][128];   // peer psums for my outputs
    __shared__ alignas(8) unsigned long long mbar;

    int tid = threadIdx.x;      // == global output index o (0..255)
    unsigned r;
    asm("mov.u32 %0, %%cluster_ctarank;" : "=r"(r));
    int b = blockIdx.x >> 1;
    unsigned peer = r ^ 1u;

    bool owner  = ((unsigned)(tid >> 7) == r);   // my output is in my half
    int  m      = tid & 127;                     // index within a half

    // Weights: W_hh[o][r*128 .. r*128+127]  (my input half, all outputs)
    float2 w2[64];
    {
        const float4* wp = (const float4*)(W_hh + (size_t)tid * H_SZ + (int)r * 128);
        #pragma unroll
        for (int j = 0; j < 32; j++) {
            float4 v = wp[j];
            w2[2 * j]     = make_float2(v.x, v.y);
            w2[2 * j + 1] = make_float2(v.z, v.w);
        }
    }

    if (tid < 128) hbuf[0][tid] = 0.f;           // h0 = 0 (local half)

    uint32_t mb = smem_u32(&mbar);
    if (tid == 0)   // 128 arrivals per phase (one per sending lane)
        asm volatile("mbarrier.init.shared.b64 [%0], %1;" :: "r"(mb), "r"(128) : "memory");

    // Remote targets (senders only use these): peer pbuf[phase][m], peer mbar
    uint32_t rp0 = mapa_peer(smem_u32(&pbuf[0][m]), peer);
    uint32_t rp1 = mapa_peer(smem_u32(&pbuf[1][m]), peer);
    uint32_t rmb = mapa_peer(mb, peer);

    const float* xpb = xp + (size_t)b * T_SZ * H_SZ + tid;
    float* hob = h1out + (size_t)b * T_SZ * H_SZ + tid;

    float pf[4];
    #pragma unroll
    for (int i = 0; i < 4; i++)
        pf[i] = __ldg(xpb + (size_t)i * H_SZ);

    // mbar + h0 visible cluster-wide before any remote traffic
    asm volatile("barrier.cluster.arrive.aligned;\n\tbarrier.cluster.wait.aligned;" ::: "memory");

    int p = 0;
    #pragma unroll 4
    for (int t = 0; t < T_SZ; t++) {
        float xv = pf[t & 3];
        int tn4 = (t + 4 < T_SZ) ? (t + 4) : (T_SZ - 1);
        pf[t & 3] = __ldg(xpb + (size_t)tn4 * H_SZ);

        // psum over LOCAL h half (warp-broadcast float4 reads, conflict-free)
        const float4* hb = (const float4*)&hbuf[p][0];
        float2 a0 = make_float2(0.f, 0.f), a1 = a0, a2 = a0, a3 = a0;
        #pragma unroll
        for (int j = 0; j < 8; j++) {
            float4 h0 = hb[4 * j];
            float4 h1v = hb[4 * j + 1];
            float4 h2 = hb[4 * j + 2];
            float4 h3 = hb[4 * j + 3];
            a0 = ffma2(make_float2(h0.x,  h0.y),  w2[8 * j],     a0);
            a1 = ffma2(make_float2(h0.z,  h0.w),  w2[8 * j + 1], a1);
            a2 = ffma2(make_float2(h1v.x, h1v.y), w2[8 * j + 2], a2);
            a3 = ffma2(make_float2(h1v.z, h1v.w), w2[8 * j + 3], a3);
            a0 = ffma2(make_float2(h2.x,  h2.y),  w2[8 * j + 4], a0);
            a1 = ffma2(make_float2(h2.z,  h2.w),  w2[8 * j + 5], a1);
            a2 = ffma2(make_float2(h3.x,  h3.y),  w2[8 * j + 6], a2);
            a3 = ffma2(make_float2(h3.z,  h3.w),  w2[8 * j + 7], a3);
        }
        float s = (a0.x + a1.x) + (a2.x + a3.x) + (a0.y + a1.y) + (a2.y + a3.y);

        if (!owner) {
            // ship psum to the peer (its output) + arrive; release orders store
            uint32_t ra = p ? rp1 : rp0;
            asm volatile("st.shared::cluster.f32 [%0], %1;" :: "r"(ra), "f"(s) : "memory");
            asm volatile("mbarrier.arrive.release.cluster.shared::cluster.b64 _, [%0];"
                         :: "r"(rmb) : "memory");
        }

        // late wait: peer psums for THIS step (phase p)
        mbar_wait_acq_cluster(mb, (uint32_t)p);

        if (owner) {
            float v = fast_tanh(s + pbuf[p][m] + xv);
            hbuf[p ^ 1][m] = v;                    // local h half for step t+1
            hob[(size_t)t * H_SZ] = v;             // h1 for layer-2 GEMM
        }
        __syncthreads();                           // step separator
        p ^= 1;
    }

    asm volatile("barrier.cluster.arrive.aligned;\n\tbarrier.cluster.wait.aligned;" ::: "memory");
}

// ---------------------------------------------------------------------------
// Layer-2 scan (frozen from R9): 128 threads/CTA, thread == output,
// no reduction, one STS + one STG per step.
// ---------------------------------------------------------------------------
__global__ __launch_bounds__(128, 1)
void rnn_scan2_kernel(const float* __restrict__ W_hh,
                      const float* __restrict__ xp,
                      float* __restrict__ out)
{
    __shared__ float obuf[2][O_SZ];

    int tid = threadIdx.x;      // == output index o
    int b = blockIdx.x;

    float2 w2[64];
    {
        const float4* wp = (const float4*)(W_hh + (size_t)tid * O_SZ);
        #pragma unroll
        for (int j = 0; j < 32; j++) {
            float4 v = wp[j];
            w2[2 * j]     = make_float2(v.x, v.y);
            w2[2 * j + 1] = make_float2(v.z, v.w);
        }
    }

    obuf[0][tid] = 0.f;

    const float* xpb = xp + (size_t)b * T_SZ * O_SZ + tid;
    float* ob = out + (size_t)b * T_SZ * O_SZ + tid;

    float pf[4];
    #pragma unroll
    for (int i = 0; i < 4; i++)
        pf[i] = __ldg(xpb + (size_t)i * O_SZ);

    __syncthreads();

    int p = 0;
    #pragma unroll 4
    for (int t = 0; t < T_SZ; t++) {
        float xv = pf[t & 3];
        int tn4 = (t + 4 < T_SZ) ? (t + 4) : (T_SZ - 1);
        pf[t & 3] = __ldg(xpb + (size_t)tn4 * O_SZ);

        const float4* hb = (const float4*)&obuf[p][0];     // warp-broadcast reads
        float2 a0 = make_float2(0.f, 0.f), a1 = a0, a2 = a0, a3 = a0;
        #pragma unroll
        for (int j = 0; j < 8; j++) {
            float4 h0 = hb[4 * j];
            float4 h1v = hb[4 * j + 1];
            float4 h2 = hb[4 * j + 2];
            float4 h3 = hb[4 * j + 3];
            a0 = ffma2(make_float2(h0.x,  h0.y),  w2[8 * j],     a0);
            a1 = ffma2(make_float2(h0.z,  h0.w),  w2[8 * j + 1], a1);
            a2 = ffma2(make_float2(h1v.x, h1v.y), w2[8 * j + 2], a2);
            a3 = ffma2(make_float2(h1v.z, h1v.w), w2[8 * j + 3], a3);
            a0 = ffma2(make_float2(h2.x,  h2.y),  w2[8 * j + 4], a0);
            a1 = ffma2(make_float2(h2.z,  h2.w),  w2[8 * j + 5], a1);
            a2 = ffma2(make_float2(h3.x,  h3.y),  w2[8 * j + 6], a2);
            a3 = ffma2(make_float2(h3.z,  h3.w),  w2[8 * j + 7], a3);
        }
        float s = (a0.x + a1.x) + (a2.x + a3.x) + (a0.y + a1.y) + (a2.y + a3.y);

        float v = fast_tanh(s + xv);                       // no reduction needed
        obuf[p ^ 1][tid] = v;                              // ONE STS
        ob[(size_t)t * O_SZ] = v;                          // ONE STG
        __syncthreads();
        p ^= 1;
    }
}

// ---------------------------------------------------------------------------
extern "C" void kernel_launch(void* const* d_in, const int* in_sizes, int n_in,
                              void* d_out, int out_size)
{
    const float* x     = (const float*)d_in[0];
    const float* W_ih1 = (const float*)d_in[1];
    const float* W_hh1 = (const float*)d_in[2];
    const float* b_ih1 = (const float*)d_in[3];
    const float* b_hh1 = (const float*)d_in[4];
    const float* W_ih2 = (const float*)d_in[5];
    const float* W_hh2 = (const float*)d_in[6];
    const float* b_ih2 = (const float*)d_in[7];
    const float* b_hh2 = (const float*)d_in[8];
    float* out = (float*)d_out;

    float *xp1, *h1, *xp2;
    cudaGetSymbolAddress((void**)&xp1, g_xp1);
    cudaGetSymbolAddress((void**)&h1,  g_h1);
    cudaGetSymbolAddress((void**)&xp2, g_xp2);

    // Phase 1: xp1 = x @ W_ih1^T + (b_ih1 + b_hh1)   [131072 x 256]
    dim3 g1(H_SZ / 128, M_SZ / 128);
    sgemm_bias_kernel<<<g1, 256>>>(x, W_ih1, b_ih1, b_hh1, xp1, I_SZ, H_SZ);

    // Phase 2: layer-1 recurrent scan (cluster-2 per batch, psum exchange)
    rnn_scan1_kernel<<<B_SZ * 2, 256>>>(W_hh1, xp1, h1);

    // Phase 3: xp2 = h1 @ W_ih2^T + (b_ih2 + b_hh2)  [131072 x 128]
    dim3 g2(O_SZ / 128, M_SZ / 128);
    sgemm_bias_kernel<<<g2, 256>>>(h1, W_ih2, b_ih2, b_hh2, xp2, H_SZ, O_SZ);

    // Phase 4: layer-2 recurrent scan, writes final output
    rnn_scan2_kernel<<<B_SZ, 128>>>(W_hh2, xp2, out);
}